// round 8
// baseline (speedup 1.0000x reference)
#include <cuda_runtime.h>
#include <math.h>

// ---------------- problem constants ----------------
#define NPIX   262144            // 512*512 pixels per image
#define NIMG   64
#define NIC    128               // image-channels: [0,64)=region, [64,128)=affinity
#define K1_BPI 32                // blocks per image in k1b
#define K1_CHUNK (NPIX / K1_BPI) // 8192 pixels per block
#define K1_GRID (NIMG * K1_BPI)  // 2048
#define NTHREADS 256
#define POS_THR 0.1f
#define FALLBACK_POS 1000.0f

// sampling for k1a: 32 chunks of 256 contiguous pixels per IC -> 8192 samples (1/32)
#define SCHUNKS 32
#define SCHUNK_STRIDE (NPIX / SCHUNKS)   // 8192

// ---------------- device state (static, zero-initialized, allocation-free) ----
// statics are zero at module load (correct for call #1); the k1b completion block
// re-zeros everything it consumes, so later calls / graph replays stay correct.
__device__ float g_thr[NIC];    // float loss threshold per IC (overwritten by k1a)
__device__ float g_p[NIC];      // positive count (exact integer-valued)
__device__ float g_ps[NIC];     // sum of loss over positives
__device__ float g_ts[NIC];     // total loss sum
__device__ float g_S[NIC];      // sum of neg losses > t
__device__ float g_C[NIC];      // count of neg losses > t (integer-valued)
__device__ unsigned g_done;     // k1b completion counter

// ---------------- helpers ----------------
__device__ __forceinline__ float warp_sum(float v) {
    #pragma unroll
    for (int o = 16; o; o >>= 1) v += __shfl_xor_sync(0xffffffffu, v, o);
    return v;
}
__device__ __forceinline__ float warp_max(float v) {
    #pragma unroll
    for (int o = 16; o; o >>= 1) v = fmaxf(v, __shfl_xor_sync(0xffffffffu, v, o));
    return v;
}

// ---------------- k1a: sampled pass -> per-IC float threshold ----------------
// block = one image-channel; 256 threads x 32 register-resident sample losses
__global__ void __launch_bounds__(NTHREADS) k1a_thresh(
    const float* __restrict__ rlab, const float* __restrict__ alab,
    const float* __restrict__ rpre, const float* __restrict__ apre,
    const float* __restrict__ mask, const int* __restrict__ neg_rto)
{
    const int ic  = blockIdx.x;
    const int img = ic & (NIMG - 1);
    const int ch  = ic >> 6;
    const float* __restrict__ lab = ch ? alab : rlab;
    const float* __restrict__ pre = ch ? apre : rpre;
    const size_t ibase = (size_t)img * NPIX;

    float loss[SCHUNKS];            // sampled losses (pos samples -> -1, excluded)
    float posc = 0.f;
    float vmax = 0.f;

    #pragma unroll
    for (int c = 0; c < SCHUNKS; ++c) {
        const size_t off = ibase + (size_t)c * SCHUNK_STRIDE + threadIdx.x;
        float L = lab[off];
        float P = pre[off];
        float M = mask[off];
        float d = P - L;
        float l = d * d * M;
        bool po = L > POS_THR;
        posc += po ? 1.f : 0.f;
        loss[c] = po ? -1.f : l;
        vmax = fmaxf(vmax, loss[c]);
    }

    // block-reduce sampled positive count and max loss
    __shared__ float shp[NTHREADS / 32], shm[NTHREADS / 32];
    const int w = threadIdx.x >> 5, ln = threadIdx.x & 31;
    float pw = warp_sum(posc);
    float mw = warp_max(vmax);
    if (ln == 0) { shp[w] = pw; shm[w] = mw; }
    __syncthreads();
    __shared__ float s_lo, s_hi, s_j;
    if (threadIdx.x == 0) {
        float ps = 0.f, mx = 0.f;
        #pragma unroll
        for (int i = 0; i < NTHREADS / 32; ++i) { ps += shp[i]; mx = fmaxf(mx, shm[i]); }
        // target sample rank: j = neg_rto * p_eff_sample ; sample is 1/32 of pixels
        float peff_s = (ps > 0.f) ? ps : (FALLBACK_POS / (float)SCHUNKS);
        s_j  = (float)(*neg_rto) * peff_s;
        s_lo = -1e-9f;
        s_hi = mx + 1e-6f;
    }
    __syncthreads();

    __shared__ float scnt[NTHREADS / 32];
    for (int iter = 0; iter < 24; ++iter) {
        const float mid = 0.5f * (s_lo + s_hi);
        float c = 0.f;
        #pragma unroll
        for (int i = 0; i < SCHUNKS; ++i) c += (loss[i] > mid) ? 1.f : 0.f;
        c = warp_sum(c);
        if (ln == 0) scnt[w] = c;
        __syncthreads();
        if (threadIdx.x == 0) {
            float tot = 0.f;
            #pragma unroll
            for (int i = 0; i < NTHREADS / 32; ++i) tot += scnt[i];
            if (tot > s_j) s_lo = mid; else s_hi = mid;
        }
        __syncthreads();
    }
    if (threadIdx.x == 0) g_thr[ic] = fmaxf(0.5f * (s_lo + s_hi), 0.f);
}

// ---------------- k1b: full streaming pass -> exact stats + S(t), C(t) --------
__global__ void __launch_bounds__(NTHREADS) k1b_scan(
    const float* __restrict__ rlab, const float* __restrict__ alab,
    const float* __restrict__ rpre, const float* __restrict__ apre,
    const float* __restrict__ mask, const int* __restrict__ neg_rto,
    float* __restrict__ out)
{
    const int blk   = blockIdx.x;
    const int img   = blk / K1_BPI;
    const int chunk = blk % K1_BPI;
    const size_t ibase = (size_t)img * NPIX;
    const int pbase = chunk * K1_CHUNK;

    const float t_r = g_thr[img];
    const float t_a = g_thr[NIMG + img];

    float p_r = 0.f, ps_r = 0.f, ts_r = 0.f, S_r = 0.f, C_r = 0.f;
    float p_a = 0.f, ps_a = 0.f, ts_a = 0.f, S_a = 0.f, C_a = 0.f;

    #pragma unroll 4
    for (int it = 0; it < K1_CHUNK / (NTHREADS * 4); ++it) {   // 8 iterations
        const int pix = pbase + it * (NTHREADS * 4) + threadIdx.x * 4;
        const size_t off = ibase + (size_t)pix;

        float4 rl = __ldcs((const float4*)(rlab + off));
        float4 rp = __ldcs((const float4*)(rpre + off));
        float4 al = __ldcs((const float4*)(alab + off));
        float4 ap = __ldcs((const float4*)(apre + off));
        float4 mk = __ldcs((const float4*)(mask + off));

        #define PROC(L, P, M, T, PC, PS, TS, SS, CC)                   \
        {   float d = (P) - (L);                                       \
            float l = d * d * (M);                                     \
            TS += l;                                                   \
            bool po = (L) > POS_THR;                                   \
            PC += po ? 1.f : 0.f;                                      \
            PS += po ? l   : 0.f;                                      \
            bool sel = (!po) && (l > (T));                             \
            SS += sel ? l   : 0.f;                                     \
            CC += sel ? 1.f : 0.f; }

        PROC(rl.x, rp.x, mk.x, t_r, p_r, ps_r, ts_r, S_r, C_r)
        PROC(rl.y, rp.y, mk.y, t_r, p_r, ps_r, ts_r, S_r, C_r)
        PROC(rl.z, rp.z, mk.z, t_r, p_r, ps_r, ts_r, S_r, C_r)
        PROC(rl.w, rp.w, mk.w, t_r, p_r, ps_r, ts_r, S_r, C_r)
        PROC(al.x, ap.x, mk.x, t_a, p_a, ps_a, ts_a, S_a, C_a)
        PROC(al.y, ap.y, mk.y, t_a, p_a, ps_a, ts_a, S_a, C_a)
        PROC(al.z, ap.z, mk.z, t_a, p_a, ps_a, ts_a, S_a, C_a)
        PROC(al.w, ap.w, mk.w, t_a, p_a, ps_a, ts_a, S_a, C_a)
        #undef PROC
    }

    // block-reduce 10 stats -> atomicAdd
    __shared__ float sh[10][NTHREADS / 32];
    float vals[10] = {p_r, ps_r, ts_r, S_r, C_r, p_a, ps_a, ts_a, S_a, C_a};
    const int w = threadIdx.x >> 5, ln = threadIdx.x & 31;
    #pragma unroll
    for (int s = 0; s < 10; ++s) {
        float v = warp_sum(vals[s]);
        if (ln == 0) sh[s][w] = v;
    }
    __syncthreads();
    if (threadIdx.x < 10) {
        float v = 0.f;
        #pragma unroll
        for (int i = 0; i < NTHREADS / 32; ++i) v += sh[threadIdx.x][i];
        const int ch = threadIdx.x / 5;            // 0: region, 1: affinity
        const int s  = threadIdx.x % 5;
        const int ic = img + ch * NIMG;
        float* tgt;
        switch (s) {
            case 0: tgt = &g_p [ic]; break;
            case 1: tgt = &g_ps[ic]; break;
            case 2: tgt = &g_ts[ic]; break;
            case 3: tgt = &g_S [ic]; break;
            default:tgt = &g_C [ic]; break;
        }
        atomicAdd(tgt, v);
    }

    // completion detection
    __shared__ unsigned s_rank;
    __syncthreads();
    if (threadIdx.x == 0) {
        __threadfence();
        s_rank = atomicAdd(&g_done, 1u);
    }
    __syncthreads();
    if (s_rank != K1_GRID - 1) return;

    // ===== completion block: assemble final scalar, re-zero state =====
    __threadfence();
    const int t = threadIdx.x;
    float v = 0.f;
    if (t < NIC) {
        const float p  = *(volatile float*)&g_p[t];
        const float ps = *(volatile float*)&g_ps[t];
        const float ts = *(volatile float*)&g_ts[t];
        const float S  = *(volatile float*)&g_S[t];
        const float C  = *(volatile float*)&g_C[t];
        const float th = g_thr[t];
        const float n  = (float)NPIX - p;

        const float pos_loss = (p > 0.f) ? ps / fmaxf(p, 1.f) : 0.f;
        const float peff = (p > 0.f) ? p : FALLBACK_POS;
        const float kf   = (float)(*neg_rto) * peff;
        const float k    = floorf(kf);

        float neg_loss;
        if ((p > 0.f) && (n < kf)) {
            neg_loss = (ts - ps) / fmaxf(n, 1.f);
        } else {
            // second-order-accurate top-k: error ~ (C - k)^2 / (2 * density)
            neg_loss = (S + (k - C) * th) / kf;
        }
        v = pos_loss + neg_loss;

        // re-zero all consumed accumulators for the next invocation / replay
        g_p[t] = 0.f; g_ps[t] = 0.f; g_ts[t] = 0.f;
        g_S[t] = 0.f; g_C[t]  = 0.f;
    }
    if (t == 0) g_done = 0u;

    __shared__ float red[NIC];
    if (t < NIC) red[t] = v;
    __syncthreads();
    #pragma unroll
    for (int o = NIC / 2; o >= 1; o >>= 1) {
        if (t < o) red[t] += red[t + o];
        __syncthreads();
    }
    if (t == 0) out[0] = red[0] / (float)NIMG;
}

// ---------------- launch ----------------
extern "C" void kernel_launch(void* const* d_in, const int* in_sizes, int n_in,
                              void* d_out, int out_size)
{
    const float* rlab = (const float*)d_in[0];
    const float* alab = (const float*)d_in[1];
    const float* rpre = (const float*)d_in[2];
    const float* apre = (const float*)d_in[3];
    const float* mask = (const float*)d_in[4];
    const int*   nrto = (const int*)  d_in[5];
    float* out = (float*)d_out;
    (void)in_sizes; (void)n_in; (void)out_size;

    k1a_thresh<<<NIC, NTHREADS>>>(rlab, alab, rpre, apre, mask, nrto);
    k1b_scan  <<<K1_GRID, NTHREADS>>>(rlab, alab, rpre, apre, mask, nrto, out);
}

// round 9
// speedup vs baseline: 1.0229x; 1.0229x over previous
#include <cuda_runtime.h>
#include <math.h>

// ---------------- problem constants ----------------
#define NPIX   262144            // 512*512 pixels per image
#define NIMG   64
#define NIC    128               // image-channels: [0,64)=region, [64,128)=affinity
#define K1_BPI 32                // blocks per image in k1b
#define K1_CHUNK (NPIX / K1_BPI) // 8192 pixels per block
#define K1_GRID (NIMG * K1_BPI)  // 2048
#define NTHREADS 256
#define POS_THR 0.1f
#define FALLBACK_POS 1000.0f

// sampling for k1a: 32 chunks of 256 contiguous pixels per IC -> 8192 samples (1/32)
#define SCHUNKS 32
#define SRATE   32               // 1/32 of pixels sampled
#define SCHUNK_STRIDE (NPIX / SCHUNKS)   // 8192

// ---------------- device state (static, zero-initialized, allocation-free) ----
// statics are zero at module load (correct for call #1); the k1b completion block
// re-zeros everything it consumes, so later calls / graph replays stay correct.
__device__ float g_thr[NIC];    // float loss threshold per IC (overwritten by k1a)
__device__ float g_rho[NIC];    // local rank density dC/dv at thr (overwritten by k1a)
__device__ float g_p[NIC];      // positive count (exact integer-valued)
__device__ float g_ps[NIC];     // sum of loss over positives
__device__ float g_ts[NIC];     // total loss sum
__device__ float g_S[NIC];      // sum of neg losses > t
__device__ float g_C[NIC];      // count of neg losses > t (integer-valued)
__device__ unsigned g_done;     // k1b completion counter

// ---------------- helpers ----------------
__device__ __forceinline__ float warp_sum(float v) {
    #pragma unroll
    for (int o = 16; o; o >>= 1) v += __shfl_xor_sync(0xffffffffu, v, o);
    return v;
}
__device__ __forceinline__ int warp_sum_i(int v) {
    #pragma unroll
    for (int o = 16; o; o >>= 1) v += __shfl_xor_sync(0xffffffffu, v, o);
    return v;
}
__device__ __forceinline__ float warp_max(float v) {
    #pragma unroll
    for (int o = 16; o; o >>= 1) v = fmaxf(v, __shfl_xor_sync(0xffffffffu, v, o));
    return v;
}

// ---------------- k1a: sampled pass -> per-IC threshold + local density -------
// block = one image-channel; 256 threads x 32 register-resident sample losses
__global__ void __launch_bounds__(NTHREADS) k1a_thresh(
    const float* __restrict__ rlab, const float* __restrict__ alab,
    const float* __restrict__ rpre, const float* __restrict__ apre,
    const float* __restrict__ mask, const int* __restrict__ neg_rto)
{
    const int ic  = blockIdx.x;
    const int img = ic & (NIMG - 1);
    const int ch  = ic >> 6;
    const float* __restrict__ lab = ch ? alab : rlab;
    const float* __restrict__ pre = ch ? apre : rpre;
    const size_t ibase = (size_t)img * NPIX;

    float loss[SCHUNKS];            // sampled losses (pos samples -> -1, excluded)
    float posc = 0.f;
    float vmax = 0.f;

    #pragma unroll
    for (int c = 0; c < SCHUNKS; ++c) {
        const size_t off = ibase + (size_t)c * SCHUNK_STRIDE + threadIdx.x;
        float L = lab[off];
        float P = pre[off];
        float M = mask[off];
        float d = P - L;
        float l = d * d * M;
        bool po = L > POS_THR;
        posc += po ? 1.f : 0.f;
        loss[c] = po ? -1.f : l;
        vmax = fmaxf(vmax, loss[c]);
    }

    // block-reduce sampled positive count and max loss
    __shared__ float shp[NTHREADS / 32], shm[NTHREADS / 32];
    const int w = threadIdx.x >> 5, ln = threadIdx.x & 31;
    float pw = warp_sum(posc);
    float mw = warp_max(vmax);
    if (ln == 0) { shp[w] = pw; shm[w] = mw; }
    __syncthreads();
    __shared__ float s_lo, s_hi, s_j, s_vmax, s_t1;
    if (threadIdx.x == 0) {
        float ps = 0.f, mx = 0.f;
        #pragma unroll
        for (int i = 0; i < NTHREADS / 32; ++i) { ps += shp[i]; mx = fmaxf(mx, shm[i]); }
        float peff_s = (ps > 0.f) ? ps : (FALLBACK_POS / (float)SRATE);
        s_j  = (float)(*neg_rto) * peff_s;       // target sample rank
        s_lo = -1e-9f;
        s_hi = mx + 1e-6f;
        s_vmax = mx;
    }
    __syncthreads();

    __shared__ float scnt[NTHREADS / 32];
    // --- bisection 1: t1 at sample rank j ---
    for (int iter = 0; iter < 24; ++iter) {
        const float mid = 0.5f * (s_lo + s_hi);
        float c = 0.f;
        #pragma unroll
        for (int i = 0; i < SCHUNKS; ++i) c += (loss[i] > mid) ? 1.f : 0.f;
        c = warp_sum(c);
        if (ln == 0) scnt[w] = c;
        __syncthreads();
        if (threadIdx.x == 0) {
            float tot = 0.f;
            #pragma unroll
            for (int i = 0; i < NTHREADS / 32; ++i) tot += scnt[i];
            if (tot > s_j) s_lo = mid; else s_hi = mid;
        }
        __syncthreads();
    }
    if (threadIdx.x == 0) {
        s_t1 = fmaxf(0.5f * (s_lo + s_hi), 0.f);
        g_thr[ic] = s_t1;
        // --- set up bisection 2: t2 at rank j + delta (deeper into the tail) ---
        s_j  = s_j + fmaxf(s_j * 0.0625f, 128.f);
        s_lo = -1e-9f;
        s_hi = s_t1 + 1e-9f;
    }
    __syncthreads();

    // --- bisection 2: t2 (t2 <= t1) for local density estimate ---
    for (int iter = 0; iter < 22; ++iter) {
        const float mid = 0.5f * (s_lo + s_hi);
        float c = 0.f;
        #pragma unroll
        for (int i = 0; i < SCHUNKS; ++i) c += (loss[i] > mid) ? 1.f : 0.f;
        c = warp_sum(c);
        if (ln == 0) scnt[w] = c;
        __syncthreads();
        if (threadIdx.x == 0) {
            float tot = 0.f;
            #pragma unroll
            for (int i = 0; i < NTHREADS / 32; ++i) tot += scnt[i];
            if (tot > s_j) s_lo = mid; else s_hi = mid;
        }
        __syncthreads();
    }
    if (threadIdx.x == 0) {
        const float t2 = fmaxf(0.5f * (s_lo + s_hi), 0.f);
        const float dv = s_t1 - t2;
        const float dj = fmaxf(s_j * 0.0625f, 128.f); // same delta as above (s_j mutated; recompute magnitude)
        // rho = full-population rank density dC/dv at t1 (counts per unit value)
        g_rho[ic] = (dv > 1e-12f) ? ((float)SRATE * dj / dv) : 3.4e38f;
    }
}

// ---------------- k1b: full streaming pass -> exact stats + S(t), C(t) --------
__global__ void __launch_bounds__(NTHREADS, 5) k1b_scan(
    const float* __restrict__ rlab, const float* __restrict__ alab,
    const float* __restrict__ rpre, const float* __restrict__ apre,
    const float* __restrict__ mask, const int* __restrict__ neg_rto,
    float* __restrict__ out)
{
    const int blk   = blockIdx.x;
    const int img   = blk / K1_BPI;
    const int chunk = blk % K1_BPI;
    const size_t ibase = (size_t)img * NPIX;
    const int pbase = chunk * K1_CHUNK;

    const float t_r = g_thr[img];
    const float t_a = g_thr[NIMG + img];

    // packed int accumulators: p in bits[16:], C in bits[:16] (max 32 each/thread)
    int   pc_r = 0, pc_a = 0;
    float ps_r = 0.f, ts_r = 0.f, S_r = 0.f;
    float ps_a = 0.f, ts_a = 0.f, S_a = 0.f;

    #pragma unroll 4
    for (int it = 0; it < K1_CHUNK / (NTHREADS * 4); ++it) {   // 8 iterations
        const int pix = pbase + it * (NTHREADS * 4) + threadIdx.x * 4;
        const size_t off = ibase + (size_t)pix;

        float4 rl = __ldcs((const float4*)(rlab + off));
        float4 rp = __ldcs((const float4*)(rpre + off));
        float4 al = __ldcs((const float4*)(alab + off));
        float4 ap = __ldcs((const float4*)(apre + off));
        float4 mk = __ldcs((const float4*)(mask + off));

        #define PROC(L, P, M, T, PC, PS, TS, SS)                       \
        {   float d = (P) - (L);                                       \
            float l = d * d * (M);                                     \
            TS += l;                                                   \
            bool po = (L) > POS_THR;                                   \
            PS += po ? l : 0.f;                                        \
            bool sel = (!po) && (l > (T));                             \
            SS += sel ? l : 0.f;                                       \
            PC += (po ? 0x10000 : 0) + (sel ? 1 : 0); }

        PROC(rl.x, rp.x, mk.x, t_r, pc_r, ps_r, ts_r, S_r)
        PROC(rl.y, rp.y, mk.y, t_r, pc_r, ps_r, ts_r, S_r)
        PROC(rl.z, rp.z, mk.z, t_r, pc_r, ps_r, ts_r, S_r)
        PROC(rl.w, rp.w, mk.w, t_r, pc_r, ps_r, ts_r, S_r)
        PROC(al.x, ap.x, mk.x, t_a, pc_a, ps_a, ts_a, S_a)
        PROC(al.y, ap.y, mk.y, t_a, pc_a, ps_a, ts_a, S_a)
        PROC(al.z, ap.z, mk.z, t_a, pc_a, ps_a, ts_a, S_a)
        PROC(al.w, ap.w, mk.w, t_a, pc_a, ps_a, ts_a, S_a)
        #undef PROC
    }

    // block-reduce: 2 packed ints + 6 floats -> atomicAdd to 10 stat slots
    __shared__ int   shi[2][NTHREADS / 32];
    __shared__ float shf[6][NTHREADS / 32];
    const int w = threadIdx.x >> 5, ln = threadIdx.x & 31;
    {
        int iv[2] = {pc_r, pc_a};
        float fv[6] = {ps_r, ts_r, S_r, ps_a, ts_a, S_a};
        #pragma unroll
        for (int s = 0; s < 2; ++s) {
            int v = warp_sum_i(iv[s]);
            if (ln == 0) shi[s][w] = v;
        }
        #pragma unroll
        for (int s = 0; s < 6; ++s) {
            float v = warp_sum(fv[s]);
            if (ln == 0) shf[s][w] = v;
        }
    }
    __syncthreads();
    if (threadIdx.x < 10) {
        const int ch = threadIdx.x / 5;            // 0: region, 1: affinity
        const int s  = threadIdx.x % 5;            // 0:p 1:ps 2:ts 3:S 4:C
        const int ic = img + ch * NIMG;
        float v;
        if (s == 0 || s == 4) {
            int tot = 0;
            #pragma unroll
            for (int i = 0; i < NTHREADS / 32; ++i) tot += shi[ch][i];
            v = (s == 0) ? (float)(tot >> 16) : (float)(tot & 0xffff);
        } else {
            const int f = ch * 3 + (s - 1);
            float t = 0.f;
            #pragma unroll
            for (int i = 0; i < NTHREADS / 32; ++i) t += shf[f][i];
            v = t;
        }
        float* tgt;
        switch (s) {
            case 0: tgt = &g_p [ic]; break;
            case 1: tgt = &g_ps[ic]; break;
            case 2: tgt = &g_ts[ic]; break;
            case 3: tgt = &g_S [ic]; break;
            default:tgt = &g_C [ic]; break;
        }
        atomicAdd(tgt, v);
    }

    // completion detection
    __shared__ unsigned s_rank;
    __syncthreads();
    if (threadIdx.x == 0) {
        __threadfence();
        s_rank = atomicAdd(&g_done, 1u);
    }
    __syncthreads();
    if (s_rank != K1_GRID - 1) return;

    // ===== completion block: assemble final scalar, re-zero state =====
    __threadfence();
    const int t = threadIdx.x;
    float v = 0.f;
    if (t < NIC) {
        const float p   = *(volatile float*)&g_p[t];
        const float ps  = *(volatile float*)&g_ps[t];
        const float ts  = *(volatile float*)&g_ts[t];
        const float S   = *(volatile float*)&g_S[t];
        const float C   = *(volatile float*)&g_C[t];
        const float th  = g_thr[t];
        const float rho = g_rho[t];
        const float n   = (float)NPIX - p;

        const float pos_loss = (p > 0.f) ? ps / fmaxf(p, 1.f) : 0.f;
        const float peff = (p > 0.f) ? p : FALLBACK_POS;
        const float kf   = (float)(*neg_rto) * peff;
        const float k    = floorf(kf);

        float neg_loss;
        if ((p > 0.f) && (n < kf)) {
            neg_loss = (ts - ps) / fmaxf(n, 1.f);
        } else {
            // top-k sum with quadratic rank-error correction:
            //   sum = S + (k-C)*t - (k-C)^2 / (2*rho)
            const float dk   = k - C;
            const float corr = (rho > 0.f) ? (dk * dk) / (2.f * rho) : 0.f;
            const float topk = fmaxf(S + dk * th - corr, 0.f);
            neg_loss = topk / kf;
        }
        v = pos_loss + neg_loss;

        // re-zero all consumed accumulators for the next invocation / replay
        g_p[t] = 0.f; g_ps[t] = 0.f; g_ts[t] = 0.f;
        g_S[t] = 0.f; g_C[t]  = 0.f;
    }
    if (t == 0) g_done = 0u;

    __shared__ float red[NIC];
    if (t < NIC) red[t] = v;
    __syncthreads();
    #pragma unroll
    for (int o = NIC / 2; o >= 1; o >>= 1) {
        if (t < o) red[t] += red[t + o];
        __syncthreads();
    }
    if (t == 0) out[0] = red[0] / (float)NIMG;
}

// ---------------- launch ----------------
extern "C" void kernel_launch(void* const* d_in, const int* in_sizes, int n_in,
                              void* d_out, int out_size)
{
    const float* rlab = (const float*)d_in[0];
    const float* alab = (const float*)d_in[1];
    const float* rpre = (const float*)d_in[2];
    const float* apre = (const float*)d_in[3];
    const float* mask = (const float*)d_in[4];
    const int*   nrto = (const int*)  d_in[5];
    float* out = (float*)d_out;
    (void)in_sizes; (void)n_in; (void)out_size;

    k1a_thresh<<<NIC, NTHREADS>>>(rlab, alab, rpre, apre, mask, nrto);
    k1b_scan  <<<K1_GRID, NTHREADS>>>(rlab, alab, rpre, apre, mask, nrto, out);
}